// round 1
// baseline (speedup 1.0000x reference)
#include <cuda_runtime.h>
#include <math.h>

// Problem constants
#define BN 2048
#define DN 3072
#define CN 10
#define MN 9

#define ALPHA  0.999999f          // 1 - C*NUM_STAB
#define NST    1e-7f
#define RS10   0.31622776601683794f  // 1/sqrt(10)

// Scratch (no allocations allowed)
__device__ __align__(16) float g_Wt[CN * DN];     // W transposed [C][D]
__device__ float g_Wg[CN * CN];                   // W^T W
__device__ float g_logits[BN * CN];

// ---------------------------------------------------------------------------
// Kernel P: blocks 0..119 transpose W -> Wt ; blocks 120..129 compute Wg rows
// ---------------------------------------------------------------------------
__global__ void __launch_bounds__(256) prep_kernel(const float* __restrict__ W) {
    int bid = blockIdx.x;
    int tid = threadIdx.x;
    if (bid < 120) {
        int idx = bid * 256 + tid;          // idx = c*3072 + d  (coalesced writes)
        int c = idx / DN;
        int d = idx - c * DN;
        g_Wt[idx] = W[d * CN + c];
    } else {
        int i = bid - 120;                  // Wg row i
        float acc[CN];
        #pragma unroll
        for (int j = 0; j < CN; j++) acc[j] = 0.f;
        for (int d = tid; d < DN; d += 256) {
            float w[CN];
            #pragma unroll
            for (int j = 0; j < CN; j++) w[j] = W[d * CN + j];
            float wi = w[i];
            #pragma unroll
            for (int j = 0; j < CN; j++) acc[j] = fmaf(wi, w[j], acc[j]);
        }
        // warp reduce
        #pragma unroll
        for (int j = 0; j < CN; j++) {
            #pragma unroll
            for (int off = 16; off > 0; off >>= 1)
                acc[j] += __shfl_xor_sync(0xffffffffu, acc[j], off);
        }
        __shared__ float smem[8][CN];
        int w_ = tid >> 5, l = tid & 31;
        if (l == 0) {
            #pragma unroll
            for (int j = 0; j < CN; j++) smem[w_][j] = acc[j];
        }
        __syncthreads();
        if (tid < CN) {
            float s = 0.f;
            #pragma unroll
            for (int k = 0; k < 8; k++) s += smem[k][tid];
            g_Wg[i * CN + tid] = s;
        }
    }
}

// ---------------------------------------------------------------------------
// Kernel A: logits = X @ W + b.  One warp computes 4 samples; lanes split K.
// Wt float4 registers reused across 4 samples (amortizes L1 traffic 4x).
// ---------------------------------------------------------------------------
__global__ void __launch_bounds__(256) logits_kernel(const float* __restrict__ data,
                                                     const float* __restrict__ bias) {
    int warp = (blockIdx.x * blockDim.x + threadIdx.x) >> 5;   // 0..511
    int lane = threadIdx.x & 31;
    int s0 = warp * 4;

    float acc[4][CN];
    #pragma unroll
    for (int s = 0; s < 4; s++)
        #pragma unroll
        for (int c = 0; c < CN; c++) acc[s][c] = 0.f;

    const float4* x0 = reinterpret_cast<const float4*>(data + (size_t)s0 * DN);
    const float4* wt = reinterpret_cast<const float4*>(g_Wt);

    #pragma unroll 2
    for (int i = 0; i < 24; i++) {
        int k4 = i * 32 + lane;             // float4 index within a row (768 per row)
        float4 xv[4];
        #pragma unroll
        for (int s = 0; s < 4; s++) xv[s] = x0[s * 768 + k4];
        #pragma unroll
        for (int c = 0; c < CN; c++) {
            float4 wv = wt[c * 768 + k4];
            #pragma unroll
            for (int s = 0; s < 4; s++) {
                acc[s][c] = fmaf(xv[s].x, wv.x, acc[s][c]);
                acc[s][c] = fmaf(xv[s].y, wv.y, acc[s][c]);
                acc[s][c] = fmaf(xv[s].z, wv.z, acc[s][c]);
                acc[s][c] = fmaf(xv[s].w, wv.w, acc[s][c]);
            }
        }
    }

    // butterfly reduce across lanes
    #pragma unroll
    for (int s = 0; s < 4; s++)
        #pragma unroll
        for (int c = 0; c < CN; c++) {
            #pragma unroll
            for (int off = 16; off > 0; off >>= 1)
                acc[s][c] += __shfl_xor_sync(0xffffffffu, acc[s][c], off);
        }

    if (lane == 0) {
        #pragma unroll
        for (int s = 0; s < 4; s++)
            #pragma unroll
            for (int c = 0; c < CN; c++)
                g_logits[(s0 + s) * CN + c] = acc[s][c] + bias[c];
    }
}

// ---------------------------------------------------------------------------
// Kernel B: per-sample epilogue.
// G = u^2 * A Wg A^T with A = diag(c1) | + c2*e9 - t*s^T  (rank structure),
// computed entirely in closed form from q = Wg s, qs = s^T Wg s.
// ---------------------------------------------------------------------------
__global__ void __launch_bounds__(32) epilogue_kernel(float* __restrict__ out) {
    int b = blockIdx.x * blockDim.x + threadIdx.x;   // 0..2047
    const float* lp = g_logits + b * CN;

    float l[CN];
    #pragma unroll
    for (int c = 0; c < CN; c++) l[c] = lp[c];

    float mx = l[0];
    #pragma unroll
    for (int c = 1; c < CN; c++) mx = fmaxf(mx, l[c]);

    float e[CN], Z = 0.f;
    #pragma unroll
    for (int c = 0; c < CN; c++) { e[c] = expf(l[c] - mx); Z += e[c]; }
    float invZ = 1.f / Z;

    float s[CN], r[CN], sumr = 0.f;
    #pragma unroll
    for (int c = 0; c < CN; c++) {
        s[c] = e[c] * invZ;
        float p = fmaf(s[c], ALPHA, NST);
        r[c] = sqrtf(p);
        sumr += r[c];
    }
    float u = 1.f - r[MN];
    float delta = 2.f * acosf(fminf(sumr * RS10, 1.f));

    // Wg in registers (broadcast loads, L1-resident)
    float wg[CN * CN];
    #pragma unroll
    for (int v = 0; v < CN * CN; v++) wg[v] = g_Wg[v];

    float q[CN];
    #pragma unroll
    for (int j = 0; j < CN; j++) {
        float a = 0.f;
        #pragma unroll
        for (int k = 0; k < CN; k++) a = fmaf(s[k], wg[k * CN + j], a);
        q[j] = a;
    }
    float qs = 0.f;
    #pragma unroll
    for (int j = 0; j < CN; j++) qs = fmaf(q[j], s[j], qs);

    float inv_u = 1.f / u;
    float c2com = ALPHA * s[MN] * inv_u * inv_u / r[MN];
    float c1[MN], c2[MN], t[MN];
    #pragma unroll
    for (int m = 0; m < MN; m++) {
        c1[m] = ALPHA * s[m] * inv_u / r[m];
        c2[m] = c2com * r[m];
        t[m]  = c1[m] + c2[m];
    }

    float col[MN];
    #pragma unroll
    for (int n = 0; n < MN; n++) col[n] = 0.f;
    float norminf = 0.f;

    #pragma unroll
    for (int m = 0; m < MN; m++) {
        float Mrow[CN];
        #pragma unroll
        for (int j = 0; j < CN; j++)
            Mrow[j] = c1[m] * wg[m * CN + j] + c2[m] * wg[MN * CN + j] - t[m] * q[j];
        float wm = c1[m] * q[m] + c2[m] * q[MN] - t[m] * qs;
        float rowsum = 0.f;
        #pragma unroll
        for (int n = 0; n < MN; n++) {
            float g  = c1[n] * Mrow[n] + c2[n] * Mrow[MN] - t[n] * wm;
            float ag = fabsf(g);
            rowsum += ag;
            col[n] += ag;
        }
        norminf = fmaxf(norminf, rowsum);
    }
    float norm1 = 0.f;
    #pragma unroll
    for (int n = 0; n < MN; n++) norm1 = fmaxf(norm1, col[n]);

    float u2 = u * u;
    float jn = u2 * sqrtf(norm1 * norminf);   // rho^2 scaling folded into norms
    out[b] = delta / (0.1f * jn);
}

// ---------------------------------------------------------------------------
extern "C" void kernel_launch(void* const* d_in, const int* in_sizes, int n_in,
                              void* d_out, int out_size) {
    const float* data = (const float*)d_in[0];   // [2048,3,32,32]
    const float* W    = (const float*)d_in[1];   // [3072,10]
    const float* bias = (const float*)d_in[2];   // [10]
    float* out = (float*)d_out;                  // [2048,1]

    prep_kernel<<<130, 256>>>(W);
    logits_kernel<<<64, 256>>>(data, bias);
    epilogue_kernel<<<64, 32>>>(out);
}

// round 2
// speedup vs baseline: 1.8816x; 1.8816x over previous
#include <cuda_runtime.h>
#include <math.h>

#define BN 2048
#define DN 3072
#define CN 10
#define MN 9

#define ALPHA  0.999999f             // 1 - C*NUM_STAB
#define NST    1e-7f
#define RS10   0.31622776601683794f  // 1/sqrt(10)

// Scratch (no allocations allowed)
__device__ __align__(16) float g_Wt[CN * DN];   // W transposed [C][D]
__device__ float g_Wg[CN * CN];                 // W^T W

// ---------------------------------------------------------------------------
// Prep: blocks 0..119 transpose W -> Wt (coalesced READS, scattered writes);
//       blocks 120..129 compute Wg rows.
// ---------------------------------------------------------------------------
__global__ void __launch_bounds__(256) prep_kernel(const float* __restrict__ W) {
    int bid = blockIdx.x;
    int tid = threadIdx.x;
    if (bid < 120) {
        int src = bid * 256 + tid;           // linear in W storage = d*10 + c
        int d = src / CN;
        int c = src - d * CN;
        g_Wt[c * DN + d] = W[src];
    } else {
        int i = bid - 120;                   // Wg row i
        float acc[CN];
        #pragma unroll
        for (int j = 0; j < CN; j++) acc[j] = 0.f;
        for (int d = tid; d < DN; d += 256) {
            float w[CN];
            #pragma unroll
            for (int j = 0; j < CN; j++) w[j] = __ldg(&W[d * CN + j]);
            float wi = w[i];
            #pragma unroll
            for (int j = 0; j < CN; j++) acc[j] = fmaf(wi, w[j], acc[j]);
        }
        #pragma unroll
        for (int j = 0; j < CN; j++) {
            #pragma unroll
            for (int off = 16; off > 0; off >>= 1)
                acc[j] += __shfl_xor_sync(0xffffffffu, acc[j], off);
        }
        __shared__ float smem[8][CN];
        int w_ = tid >> 5, l = tid & 31;
        if (l == 0) {
            #pragma unroll
            for (int j = 0; j < CN; j++) smem[w_][j] = acc[j];
        }
        __syncthreads();
        if (tid < CN) {
            float s = 0.f;
            #pragma unroll
            for (int k = 0; k < 8; k++) s += smem[k][tid];
            g_Wg[i * CN + tid] = s;
        }
    }
}

// ---------------------------------------------------------------------------
// Fused main kernel: logits GEMM + per-sample epilogue.
// Grid: 128 blocks x 256 threads. Block handles 16 samples.
// Warp layout: wid = octet(1b) | kidx(2b). Warp covers 8 samples
// (octet selects which 8) over K-chunk kidx (768 floats).
// Lane layout: sgrp = lane>>3 (sample pair), klane = lane&7 (K split).
// ---------------------------------------------------------------------------
__global__ void __launch_bounds__(256) main_kernel(const float* __restrict__ data,
                                                   const float* __restrict__ bias,
                                                   float* __restrict__ out) {
    __shared__ float sm[4][16][CN];          // [kidx][local sample][class]

    const int tid   = threadIdx.x;
    const int wid   = tid >> 5;
    const int lane  = tid & 31;
    const int octet = wid & 1;               // which 8-sample group
    const int kidx  = wid >> 1;              // which K quarter
    const int sgrp  = lane >> 3;             // sample pair within octet
    const int klane = lane & 7;              // K split within warp

    const int ls  = octet * 8 + sgrp * 2;    // local sample index (pair base)
    const int s0  = blockIdx.x * 16 + ls;    // global sample

    const float4* __restrict__ x0 = reinterpret_cast<const float4*>(data) + (size_t)s0 * 768;
    const float4* __restrict__ x1 = x0 + 768;
    const float4* __restrict__ wt = reinterpret_cast<const float4*>(g_Wt);

    float a0[CN], a1[CN];
    #pragma unroll
    for (int c = 0; c < CN; c++) { a0[c] = 0.f; a1[c] = 0.f; }

    const int kbase = kidx * 192 + klane;    // float4 index, chunk = 192 float4

    #pragma unroll 4
    for (int i = 0; i < 24; i++) {
        int k4 = kbase + i * 8;
        float4 xv0 = x0[k4];
        float4 xv1 = x1[k4];
        #pragma unroll
        for (int c = 0; c < CN; c++) {
            float4 wv = wt[c * 768 + k4];
            a0[c] = fmaf(xv0.x, wv.x, a0[c]);
            a0[c] = fmaf(xv0.y, wv.y, a0[c]);
            a0[c] = fmaf(xv0.z, wv.z, a0[c]);
            a0[c] = fmaf(xv0.w, wv.w, a0[c]);
            a1[c] = fmaf(xv1.x, wv.x, a1[c]);
            a1[c] = fmaf(xv1.y, wv.y, a1[c]);
            a1[c] = fmaf(xv1.z, wv.z, a1[c]);
            a1[c] = fmaf(xv1.w, wv.w, a1[c]);
        }
    }

    // reduce across the 8 klanes (xor 1,2,4 stay within the klane group)
    #pragma unroll
    for (int c = 0; c < CN; c++) {
        #pragma unroll
        for (int off = 4; off > 0; off >>= 1) {
            a0[c] += __shfl_xor_sync(0xffffffffu, a0[c], off);
            a1[c] += __shfl_xor_sync(0xffffffffu, a1[c], off);
        }
    }

    if (klane == 0) {
        #pragma unroll
        for (int c = 0; c < CN; c++) {
            sm[kidx][ls][c]     = a0[c];
            sm[kidx][ls + 1][c] = a1[c];
        }
    }
    __syncthreads();

    // ---------------- fused epilogue: 16 threads, one per sample -----------
    if (tid < 16) {
        float l[CN];
        #pragma unroll
        for (int c = 0; c < CN; c++)
            l[c] = bias[c] + sm[0][tid][c] + sm[1][tid][c] + sm[2][tid][c] + sm[3][tid][c];

        float mx = l[0];
        #pragma unroll
        for (int c = 1; c < CN; c++) mx = fmaxf(mx, l[c]);

        float e[CN], Z = 0.f;
        #pragma unroll
        for (int c = 0; c < CN; c++) { e[c] = expf(l[c] - mx); Z += e[c]; }
        float invZ = 1.f / Z;

        float s[CN], r[CN], sumr = 0.f;
        #pragma unroll
        for (int c = 0; c < CN; c++) {
            s[c] = e[c] * invZ;
            float p = fmaf(s[c], ALPHA, NST);
            r[c] = sqrtf(p);
            sumr += r[c];
        }
        float u = 1.f - r[MN];
        float delta = 2.f * acosf(fminf(sumr * RS10, 1.f));

        float wg[CN * CN];
        #pragma unroll
        for (int v = 0; v < CN * CN; v++) wg[v] = __ldg(&g_Wg[v]);

        float q[CN];
        #pragma unroll
        for (int j = 0; j < CN; j++) {
            float a = 0.f;
            #pragma unroll
            for (int k = 0; k < CN; k++) a = fmaf(s[k], wg[k * CN + j], a);
            q[j] = a;
        }
        float qs = 0.f;
        #pragma unroll
        for (int j = 0; j < CN; j++) qs = fmaf(q[j], s[j], qs);

        float inv_u = 1.f / u;
        float c2com = ALPHA * s[MN] * inv_u * inv_u / r[MN];
        float c1[MN], c2[MN], t[MN];
        #pragma unroll
        for (int m = 0; m < MN; m++) {
            c1[m] = ALPHA * s[m] * inv_u / r[m];
            c2[m] = c2com * r[m];
            t[m]  = c1[m] + c2[m];
        }

        float col[MN];
        #pragma unroll
        for (int n = 0; n < MN; n++) col[n] = 0.f;
        float norminf = 0.f;

        #pragma unroll
        for (int m = 0; m < MN; m++) {
            float Mrow[CN];
            #pragma unroll
            for (int j = 0; j < CN; j++)
                Mrow[j] = c1[m] * wg[m * CN + j] + c2[m] * wg[MN * CN + j] - t[m] * q[j];
            float wm = c1[m] * q[m] + c2[m] * q[MN] - t[m] * qs;
            float rowsum = 0.f;
            #pragma unroll
            for (int n = 0; n < MN; n++) {
                float g  = c1[n] * Mrow[n] + c2[n] * Mrow[MN] - t[n] * wm;
                float ag = fabsf(g);
                rowsum += ag;
                col[n] += ag;
            }
            norminf = fmaxf(norminf, rowsum);
        }
        float norm1 = 0.f;
        #pragma unroll
        for (int n = 0; n < MN; n++) norm1 = fmaxf(norm1, col[n]);

        float u2 = u * u;
        float jn = u2 * sqrtf(norm1 * norminf);
        out[blockIdx.x * 16 + tid] = delta / (0.1f * jn);
    }
}

// ---------------------------------------------------------------------------
extern "C" void kernel_launch(void* const* d_in, const int* in_sizes, int n_in,
                              void* d_out, int out_size) {
    const float* data = (const float*)d_in[0];   // [2048,3,32,32]
    const float* W    = (const float*)d_in[1];   // [3072,10]
    const float* bias = (const float*)d_in[2];   // [10]
    float* out = (float*)d_out;                  // [2048,1]

    prep_kernel<<<130, 256>>>(W);
    main_kernel<<<128, 256>>>(data, bias, out);
}